// round 16
// baseline (speedup 1.0000x reference)
#include <cuda_runtime.h>
#include <cuda_bf16.h>
#include <math.h>
#include <stdint.h>

// Problem constants (fixed by reference)
#define B_  128
#define T_  128
#define D_  256
#define H_  1024
#define O_  1024
#define G4  (4 * H_)   // 4096

// ---------------------------------------------------------------------------
// Scratch (device globals — no runtime allocation allowed)
// ---------------------------------------------------------------------------
__device__ float          g_xg[(size_t)T_ * B_ * G4];   // 256 MB: xg[m=t*B+b][n permuted]
__device__ float          g_h[B_ * H_];
__device__ float          g_c[B_ * H_];
__device__ __nv_bfloat16  g_hhi[B_ * H_];
__device__ __nv_bfloat16  g_hlo[B_ * H_];
__device__ __nv_bfloat16  g_Whp_hi[(size_t)G4 * H_];    // gate-permuted rows
__device__ __nv_bfloat16  g_Whp_lo[(size_t)G4 * H_];
__device__ __nv_bfloat16  g_xhi[(size_t)T_ * B_ * D_];  // x in m-order, split
__device__ __nv_bfloat16  g_xlo[(size_t)T_ * B_ * D_];
__device__ __nv_bfloat16  g_Wxphi[(size_t)G4 * D_];     // gate-permuted rows, split
__device__ __nv_bfloat16  g_Wxplo[(size_t)G4 * D_];
__device__ float          g_bxp[G4];

// ---------------------------------------------------------------------------
// PTX helpers — sm_80-era only (compute_103-safe): mma.sync / ldmatrix / cp.async
// ---------------------------------------------------------------------------
__device__ __forceinline__ uint32_t smem_u32(const void* p) {
    uint32_t a;
    asm("{ .reg .u64 t; cvta.to.shared.u64 t, %1; cvt.u32.u64 %0, t; }"
        : "=r"(a) : "l"(p));
    return a;
}

__device__ __forceinline__ void mma16816(float* d, const uint32_t* a,
                                         uint32_t b0, uint32_t b1) {
    asm volatile(
        "mma.sync.aligned.m16n8k16.row.col.f32.bf16.bf16.f32 "
        "{%0,%1,%2,%3}, {%4,%5,%6,%7}, {%8,%9}, {%0,%1,%2,%3};"
        : "+f"(d[0]), "+f"(d[1]), "+f"(d[2]), "+f"(d[3])
        : "r"(a[0]), "r"(a[1]), "r"(a[2]), "r"(a[3]), "r"(b0), "r"(b1));
}

__device__ __forceinline__ void ldsm4(uint32_t* r, uint32_t addr) {
    asm volatile("ldmatrix.sync.aligned.m8n8.x4.shared.b16 {%0,%1,%2,%3}, [%4];"
        : "=r"(r[0]), "=r"(r[1]), "=r"(r[2]), "=r"(r[3]) : "r"(addr));
}

__device__ __forceinline__ void cpa16(uint32_t d, const void* s) {
    asm volatile("cp.async.cg.shared.global [%0], [%1], 16;"
                 :: "r"(d), "l"(s) : "memory");
}
#define CP_COMMIT() asm volatile("cp.async.commit_group;" ::: "memory")
#define CP_WAIT(n)  asm volatile("cp.async.wait_group %0;" :: "n"(n) : "memory")

// XOR swizzle: 16B column index XORed with row%8 -> conflict-free store + ldmatrix
__device__ __forceinline__ uint32_t sw_off(int r, int c16) {
    return (uint32_t)(r * 128 + ((c16 ^ (r & 7)) << 4));
}

// ---------------------------------------------------------------------------
// Shared GEMM machinery, templated on A-rows.
// SMEM buffer layout (per buffer): Ahi[AROWS][64] | Alo | Bhi[64][64] | Blo
//   bytes: AROWS*128 each A part, 8192 each B part.
// ---------------------------------------------------------------------------
template <int AROWS>
__device__ __forceinline__ void load_chunk(
    uint32_t buf,
    const __nv_bfloat16* __restrict__ Ahi, const __nv_bfloat16* __restrict__ Alo,
    int lda,
    const __nv_bfloat16* __restrict__ Bhi, const __nv_bfloat16* __restrict__ Blo,
    int ldb, int k0, int tid)
{
    constexpr uint32_t ABYTES = AROWS * 128;
#pragma unroll
    for (int i = 0; i < AROWS * 8 / 256; i++) {     // A: AROWS rows x 8 vec16
        int vec = tid + i * 256;
        int r = vec >> 3, c = vec & 7;
        uint32_t d = buf + sw_off(r, c);
        size_t off = (size_t)r * lda + k0 + c * 8;
        cpa16(d,          Ahi + off);
        cpa16(d + ABYTES, Alo + off);
    }
#pragma unroll
    for (int i = 0; i < 2; i++) {                   // B: 64 rows x 8 vec16
        int vec = tid + i * 256;
        int r = vec >> 3, c = vec & 7;
        uint32_t d = buf + 2 * ABYTES + sw_off(r, c);
        size_t off = (size_t)r * ldb + k0 + c * 8;
        cpa16(d,         Bhi + off);
        cpa16(d + 8192,  Blo + off);
    }
}

// Warp tile: (MT*16) x 16. acc[mt*2+nt][4]. Term-major MMA issue so dependent
// writes to the same accumulator are separated by 2*MT-1 independent MMAs.
template <int AROWS, int MT>
__device__ __forceinline__ void compute_chunk(uint32_t buf, int wm, int wn,
                                              int lane, float (*acc)[4])
{
    constexpr uint32_t ABYTES = AROWS * 128;
    const int lr = (lane & 7) + ((lane >> 3) & 1) * 8;  // row-within-16
    const int lc = lane >> 4;                           // 16B col select
#pragma unroll
    for (int kk = 0; kk < 4; kk++) {
        const int c16 = kk * 2 + lc;
        uint32_t bh[4], bl[4];
        const int brow = wn * 16 + lr;
        ldsm4(bh, buf + 2 * ABYTES + sw_off(brow, c16));
        ldsm4(bl, buf + 2 * ABYTES + 8192 + sw_off(brow, c16));

        uint32_t ah[MT][4], al[MT][4];
#pragma unroll
        for (int mt = 0; mt < MT; mt++) {
            const int arow = wm * (MT * 16) + mt * 16 + lr;
            ldsm4(ah[mt], buf + sw_off(arow, c16));
            ldsm4(al[mt], buf + ABYTES + sw_off(arow, c16));
        }
        // term 1: hi*hi
#pragma unroll
        for (int mt = 0; mt < MT; mt++) {
            mma16816(acc[mt * 2 + 0], ah[mt], bh[0], bh[2]);
            mma16816(acc[mt * 2 + 1], ah[mt], bh[1], bh[3]);
        }
        // term 2: hi*lo
#pragma unroll
        for (int mt = 0; mt < MT; mt++) {
            mma16816(acc[mt * 2 + 0], ah[mt], bl[0], bl[2]);
            mma16816(acc[mt * 2 + 1], ah[mt], bl[1], bl[3]);
        }
        // term 3: lo*hi
#pragma unroll
        for (int mt = 0; mt < MT; mt++) {
            mma16816(acc[mt * 2 + 0], al[mt], bh[0], bh[2]);
            mma16816(acc[mt * 2 + 1], al[mt], bh[1], bh[3]);
        }
    }
}

// ---------------------------------------------------------------------------
// Init: zero h (fp32 + bf16 splits) and c
// ---------------------------------------------------------------------------
__global__ void zero_state_kernel() {
    int i = blockIdx.x * blockDim.x + threadIdx.x;
    if (i < B_ * H_) {
        g_h[i] = 0.0f;
        g_c[i] = 0.0f;
        g_hhi[i] = __float2bfloat16(0.0f);
        g_hlo[i] = __float2bfloat16(0.0f);
    }
}

// ---------------------------------------------------------------------------
// Prep: gate-permute + bf16-split Wh and Wx; permute bx; convert x to m-order.
// permuted row p = 4*j + gate ; original row = gate*H + j
// ---------------------------------------------------------------------------
__global__ void prep_kernel(const float* __restrict__ Wh,
                            const float* __restrict__ Wx,
                            const float* __restrict__ bx,
                            const float* __restrict__ x)
{
    int i = blockIdx.x * blockDim.x + threadIdx.x;
    if (i < G4 * H_) {                       // Wh: 4096 x 1024
        int p = i >> 10;
        int k = i & (H_ - 1);
        int orig = ((p & 3) << 10) + (p >> 2);
        float w = Wh[(size_t)orig * H_ + k];
        __nv_bfloat16 hi = __float2bfloat16(w);
        g_Whp_hi[i] = hi;
        g_Whp_lo[i] = __float2bfloat16(w - __bfloat162float(hi));
    }
    if (i < T_ * B_ * D_) {                  // x -> m-order split
        int m = i >> 8;
        int k = i & (D_ - 1);
        int t = m >> 7;
        int b = m & 127;
        float v = x[((size_t)b * T_ + t) * D_ + k];
        __nv_bfloat16 hi = __float2bfloat16(v);
        g_xhi[i] = hi;
        g_xlo[i] = __float2bfloat16(v - __bfloat162float(hi));
    }
    if (i < G4 * D_) {                       // Wx: 4096 x 256
        int p = i >> 8;
        int k = i & (D_ - 1);
        int orig = ((p & 3) << 10) + (p >> 2);
        float w = Wx[(size_t)orig * D_ + k];
        __nv_bfloat16 hi = __float2bfloat16(w);
        g_Wxphi[i] = hi;
        g_Wxplo[i] = __float2bfloat16(w - __bfloat162float(hi));
    }
    if (i < G4) {
        int orig = ((i & 3) << 10) + (i >> 2);
        g_bxp[i] = bx[orig];
    }
}

// ---------------------------------------------------------------------------
// xg GEMM: g_xg[m][n] = xsplit[m] . Wxpsplit[n] + bxp[n]
// Grid: (4096/64, 16384/128) = (64, 128). K = 256 = 4 chunks. AROWS=128, MT=4.
// ---------------------------------------------------------------------------
#define XG_BUF (2 * 128 * 128 + 2 * 8192)    // 49152
#define XG_SMEM (2 * XG_BUF)                 // 98304

__global__ void __launch_bounds__(256) xg_gemm_kernel()
{
    extern __shared__ char smem[];
    const uint32_t sb = smem_u32(smem);
    const int tid = threadIdx.x, lane = tid & 31, wid = tid >> 5;
    const int wm = wid & 1, wn = wid >> 1;
    const int n0 = blockIdx.x * 64;
    const int m0 = blockIdx.y * 128;

    const __nv_bfloat16* Ahi = g_xhi   + (size_t)m0 * D_;
    const __nv_bfloat16* Alo = g_xlo   + (size_t)m0 * D_;
    const __nv_bfloat16* Bhi = g_Wxphi + (size_t)n0 * D_;
    const __nv_bfloat16* Blo = g_Wxplo + (size_t)n0 * D_;

    float acc[8][4];
#pragma unroll
    for (int i = 0; i < 8; i++)
#pragma unroll
        for (int j = 0; j < 4; j++) acc[i][j] = 0.0f;

    load_chunk<128>(sb, Ahi, Alo, D_, Bhi, Blo, D_, 0, tid);
    CP_COMMIT();
#pragma unroll
    for (int c = 0; c < 4; c++) {
        if (c < 3) {
            load_chunk<128>(sb + ((c + 1) & 1) * XG_BUF, Ahi, Alo, D_,
                            Bhi, Blo, D_, (c + 1) * 64, tid);
            CP_COMMIT();
            CP_WAIT(1);
        } else {
            CP_WAIT(0);
        }
        __syncthreads();
        compute_chunk<128, 4>(sb + (c & 1) * XG_BUF, wm, wn, lane, acc);
        __syncthreads();
    }

#pragma unroll
    for (int mt = 0; mt < 4; mt++)
#pragma unroll
        for (int nt = 0; nt < 2; nt++) {
            int r   = m0 + wm * 64 + mt * 16 + (lane >> 2);
            int col = n0 + wn * 16 + nt * 8 + (lane & 3) * 2;
            float b0 = g_bxp[col], b1 = g_bxp[col + 1];
            const float* a = acc[mt * 2 + nt];
            *(float2*)(g_xg + (size_t)r * G4 + col) =
                make_float2(a[0] + b0, a[1] + b1);
            *(float2*)(g_xg + (size_t)(r + 8) * G4 + col) =
                make_float2(a[2] + b0, a[3] + b1);
        }
}

// ---------------------------------------------------------------------------
// Recurrent step: raw = h @ Whp^T (split-bf16 HMMA) + fused LSTM cell.
// Grid: (64, 2) = 128 CTAs x 256 threads. CTA tile: M=64 (batch) x N=64.
// AROWS=64, MT=2. SMEM: 2 x 32768.
// ---------------------------------------------------------------------------
#define REC_BUF (2 * 64 * 128 + 2 * 8192)    // 32768
#define REC_SMEM (2 * REC_BUF)               // 65536

__global__ void __launch_bounds__(256) rec_step_kernel(const float* __restrict__ xg_t)
{
    extern __shared__ char smem[];
    const uint32_t sb = smem_u32(smem);
    const int tid = threadIdx.x, lane = tid & 31, wid = tid >> 5;
    const int wm = wid & 1, wn = wid >> 1;
    const int n0 = blockIdx.x * 64;
    const int m0 = blockIdx.y * 64;

    const __nv_bfloat16* Ahi = g_hhi + (size_t)m0 * H_;
    const __nv_bfloat16* Alo = g_hlo + (size_t)m0 * H_;
    const __nv_bfloat16* Bhi = g_Whp_hi + (size_t)n0 * H_;
    const __nv_bfloat16* Blo = g_Whp_lo + (size_t)n0 * H_;

    float acc[4][4];
#pragma unroll
    for (int i = 0; i < 4; i++)
#pragma unroll
        for (int j = 0; j < 4; j++) acc[i][j] = 0.0f;

    load_chunk<64>(sb, Ahi, Alo, H_, Bhi, Blo, H_, 0, tid);
    CP_COMMIT();
    for (int c = 0; c < 16; c++) {
        if (c < 15) {
            load_chunk<64>(sb + ((c + 1) & 1) * REC_BUF, Ahi, Alo, H_,
                           Bhi, Blo, H_, (c + 1) * 64, tid);
            CP_COMMIT();
            CP_WAIT(1);
        } else {
            CP_WAIT(0);
        }
        __syncthreads();
        compute_chunk<64, 2>(sb + (c & 1) * REC_BUF, wm, wn, lane, acc);
        __syncthreads();
    }

    // Stage C in SMEM (stride 65 floats; reuses buffer region)
    float* Cs = (float*)smem;
#pragma unroll
    for (int mt = 0; mt < 2; mt++)
#pragma unroll
        for (int nt = 0; nt < 2; nt++) {
            int r  = wm * 32 + mt * 16 + (lane >> 2);
            int cc = wn * 16 + nt * 8 + (lane & 3) * 2;
            const float* a = acc[mt * 2 + nt];
            Cs[r * 65 + cc]           = a[0];
            Cs[r * 65 + cc + 1]       = a[1];
            Cs[(r + 8) * 65 + cc]     = a[2];
            Cs[(r + 8) * 65 + cc + 1] = a[3];
        }
    __syncthreads();

    // Fused LSTM cell: 256 threads, 64 rows x 4 threads, 4 units each
    {
        const int br = tid >> 2;                 // 0..63 local batch row
        const int u0 = (tid & 3) * 4;            // unit group base
        const int b = m0 + br;
        const float4* xg4 = (const float4*)(xg_t + (size_t)b * G4 + n0);
        const int jbase = n0 >> 2;
#pragma unroll
        for (int uu = 0; uu < 4; uu++) {
            int u = u0 + uu;
            float4 xv = xg4[u];
            float gg = Cs[br * 65 + 4 * u + 0] + xv.x;
            float ii = Cs[br * 65 + 4 * u + 1] + xv.y;
            float ff = Cs[br * 65 + 4 * u + 2] + xv.z;
            float oo = Cs[br * 65 + 4 * u + 3] + xv.w;
            gg = tanhf(gg);
            ii = 1.0f / (1.0f + expf(-ii));
            ff = 1.0f / (1.0f + expf(-ff));
            oo = 1.0f / (1.0f + expf(-oo));
            int idx = b * H_ + jbase + u;
            float cn = fmaf(gg, ii, g_c[idx] * ff);
            g_c[idx] = cn;
            float hv = tanhf(cn) * oo;
            g_h[idx] = hv;
            __nv_bfloat16 hi = __float2bfloat16(hv);
            g_hhi[idx] = hi;
            g_hlo[idx] = __float2bfloat16(hv - __bfloat162float(hi));
        }
    }
}

// ---------------------------------------------------------------------------
// Final projection + softmax: one block per batch row
// ---------------------------------------------------------------------------
__global__ void __launch_bounds__(256) proj_softmax_kernel(
    const float* __restrict__ h, const float* __restrict__ Wp,
    const float* __restrict__ bp, float* __restrict__ out)
{
    __shared__ float hs[H_];
    __shared__ float logits[O_];
    __shared__ float red[8];

    const int b = blockIdx.x;
    const int tid = threadIdx.x;
    const int lane = tid & 31;
    const int warp = tid >> 5;

    for (int k = tid; k < H_; k += 256) hs[k] = h[b * H_ + k];
    __syncthreads();

    for (int o = warp; o < O_; o += 8) {
        const float4* w = (const float4*)(Wp + (size_t)o * H_);
        const float4* hv4 = (const float4*)hs;
        float s = 0.0f;
        for (int k4 = lane; k4 < H_ / 4; k4 += 32) {
            float4 wv = w[k4];
            float4 hv = hv4[k4];
            s = fmaf(wv.x, hv.x, s);
            s = fmaf(wv.y, hv.y, s);
            s = fmaf(wv.z, hv.z, s);
            s = fmaf(wv.w, hv.w, s);
        }
#pragma unroll
        for (int d = 16; d; d >>= 1) s += __shfl_xor_sync(0xFFFFFFFFu, s, d);
        if (lane == 0) logits[o] = s + bp[o];
    }
    __syncthreads();

    float mx = -INFINITY;
    for (int o = tid; o < O_; o += 256) mx = fmaxf(mx, logits[o]);
#pragma unroll
    for (int d = 16; d; d >>= 1) mx = fmaxf(mx, __shfl_xor_sync(0xFFFFFFFFu, mx, d));
    if (lane == 0) red[warp] = mx;
    __syncthreads();
    if (warp == 0) {
        float v = (lane < 8) ? red[lane] : -INFINITY;
#pragma unroll
        for (int d = 4; d; d >>= 1) v = fmaxf(v, __shfl_xor_sync(0xFFFFFFFFu, v, d));
        if (lane == 0) red[0] = v;
    }
    __syncthreads();
    mx = red[0];
    __syncthreads();

    float sm = 0.0f;
    for (int o = tid; o < O_; o += 256) {
        float e = expf(logits[o] - mx);
        logits[o] = e;
        sm += e;
    }
#pragma unroll
    for (int d = 16; d; d >>= 1) sm += __shfl_xor_sync(0xFFFFFFFFu, sm, d);
    if (lane == 0) red[warp] = sm;
    __syncthreads();
    if (warp == 0) {
        float v = (lane < 8) ? red[lane] : 0.0f;
#pragma unroll
        for (int d = 4; d; d >>= 1) v += __shfl_xor_sync(0xFFFFFFFFu, v, d);
        if (lane == 0) red[0] = v;
    }
    __syncthreads();
    float inv = 1.0f / red[0];

    for (int o = tid; o < O_; o += 256)
        out[(size_t)b * O_ + o] = logits[o] * inv;
}

// ---------------------------------------------------------------------------
// kernel_launch
// Inputs: x[B,T,D], Wx[4H,D], bx[4H], Wh[4H,H], Wp[O,H], bp[O]
// ---------------------------------------------------------------------------
extern "C" void kernel_launch(void* const* d_in, const int* in_sizes, int n_in,
                              void* d_out, int out_size)
{
    (void)in_sizes; (void)n_in; (void)out_size;
    const float* x  = (const float*)d_in[0];
    const float* Wx = (const float*)d_in[1];
    const float* bx = (const float*)d_in[2];
    const float* Wh = (const float*)d_in[3];
    const float* Wp = (const float*)d_in[4];
    const float* bp = (const float*)d_in[5];
    float* out = (float*)d_out;

    cudaFuncSetAttribute(rec_step_kernel,
                         cudaFuncAttributeMaxDynamicSharedMemorySize, REC_SMEM);
    cudaFuncSetAttribute(xg_gemm_kernel,
                         cudaFuncAttributeMaxDynamicSharedMemorySize, XG_SMEM);

    float *xg, *h;
    cudaGetSymbolAddress((void**)&xg, g_xg);
    cudaGetSymbolAddress((void**)&h,  g_h);

    // 1. zero state
    zero_state_kernel<<<(B_ * H_ + 255) / 256, 256>>>();

    // 2. weight/x prep (gate permutation + bf16 split)
    prep_kernel<<<(G4 * H_ + 255) / 256, 256>>>(Wh, Wx, bx, x);

    // 3. xg = xsplit @ Wxpsplit^T + bxp  (HMMA, permuted gate columns)
    {
        dim3 grid(G4 / 64, (T_ * B_) / 128);
        xg_gemm_kernel<<<grid, 256, XG_SMEM>>>();
    }

    // 4. recurrence: HMMA GEMM + fused cell, one launch per step, 128 CTAs
    {
        dim3 grid(G4 / 64, B_ / 64);
        for (int t = 0; t < T_; t++) {
            rec_step_kernel<<<grid, 256, REC_SMEM>>>(xg + (size_t)t * B_ * G4);
        }
    }

    // 5. projection + softmax
    proj_softmax_kernel<<<B_, 256>>>(h, Wp, bp, out);
}

// round 17
// speedup vs baseline: 1.1280x; 1.1280x over previous
#include <cuda_runtime.h>
#include <cuda_bf16.h>
#include <math.h>
#include <stdint.h>

// Problem constants (fixed by reference)
#define B_  128
#define T_  128
#define D_  256
#define H_  1024
#define O_  1024
#define G4  (4 * H_)   // 4096

// ---------------------------------------------------------------------------
// Scratch (device globals — no runtime allocation allowed)
// ---------------------------------------------------------------------------
__device__ float          g_xg[(size_t)T_ * B_ * G4];   // 256 MB: xg[m=t*B+b][n permuted]
__device__ float          g_h[B_ * H_];
__device__ float          g_c[B_ * H_];
__device__ __nv_bfloat16  g_hhi[B_ * H_];
__device__ __nv_bfloat16  g_hlo[B_ * H_];
__device__ __nv_bfloat16  g_Whp_hi[(size_t)G4 * H_];    // gate-permuted rows
__device__ __nv_bfloat16  g_Whp_lo[(size_t)G4 * H_];
__device__ __nv_bfloat16  g_xhi[(size_t)T_ * B_ * D_];  // x in m-order, split
__device__ __nv_bfloat16  g_xlo[(size_t)T_ * B_ * D_];
__device__ __nv_bfloat16  g_Wxphi[(size_t)G4 * D_];     // gate-permuted rows, split
__device__ __nv_bfloat16  g_Wxplo[(size_t)G4 * D_];
__device__ float          g_bxp[G4];

// ---------------------------------------------------------------------------
// PTX helpers — sm_80-era only (compute_103-safe): mma.sync / ldmatrix / cp.async
// ---------------------------------------------------------------------------
__device__ __forceinline__ uint32_t smem_u32(const void* p) {
    uint32_t a;
    asm("{ .reg .u64 t; cvta.to.shared.u64 t, %1; cvt.u32.u64 %0, t; }"
        : "=r"(a) : "l"(p));
    return a;
}

__device__ __forceinline__ void mma16816(float* d, const uint32_t* a,
                                         uint32_t b0, uint32_t b1) {
    asm volatile(
        "mma.sync.aligned.m16n8k16.row.col.f32.bf16.bf16.f32 "
        "{%0,%1,%2,%3}, {%4,%5,%6,%7}, {%8,%9}, {%0,%1,%2,%3};"
        : "+f"(d[0]), "+f"(d[1]), "+f"(d[2]), "+f"(d[3])
        : "r"(a[0]), "r"(a[1]), "r"(a[2]), "r"(a[3]), "r"(b0), "r"(b1));
}

__device__ __forceinline__ void ldsm4(uint32_t* r, uint32_t addr) {
    asm volatile("ldmatrix.sync.aligned.m8n8.x4.shared.b16 {%0,%1,%2,%3}, [%4];"
        : "=r"(r[0]), "=r"(r[1]), "=r"(r[2]), "=r"(r[3]) : "r"(addr));
}

__device__ __forceinline__ void cpa16(uint32_t d, const void* s) {
    asm volatile("cp.async.cg.shared.global [%0], [%1], 16;"
                 :: "r"(d), "l"(s) : "memory");
}
#define CP_COMMIT() asm volatile("cp.async.commit_group;" ::: "memory")
#define CP_WAIT(n)  asm volatile("cp.async.wait_group %0;" :: "n"(n) : "memory")

// XOR swizzle: 16B column index XORed with row%8 -> conflict-free store + ldmatrix
__device__ __forceinline__ uint32_t sw_off(int r, int c16) {
    return (uint32_t)(r * 128 + ((c16 ^ (r & 7)) << 4));
}

// ---------------------------------------------------------------------------
// xg GEMM machinery (256 threads, 8 warps, MT=4) — unchanged from R16
// buffer: Ahi[128][64] | Alo | Bhi[64][64] | Blo
// ---------------------------------------------------------------------------
template <int AROWS>
__device__ __forceinline__ void load_chunk(
    uint32_t buf,
    const __nv_bfloat16* __restrict__ Ahi, const __nv_bfloat16* __restrict__ Alo,
    int lda,
    const __nv_bfloat16* __restrict__ Bhi, const __nv_bfloat16* __restrict__ Blo,
    int ldb, int k0, int tid)
{
    constexpr uint32_t ABYTES = AROWS * 128;
#pragma unroll
    for (int i = 0; i < AROWS * 8 / 256; i++) {
        int vec = tid + i * 256;
        int r = vec >> 3, c = vec & 7;
        uint32_t d = buf + sw_off(r, c);
        size_t off = (size_t)r * lda + k0 + c * 8;
        cpa16(d,          Ahi + off);
        cpa16(d + ABYTES, Alo + off);
    }
#pragma unroll
    for (int i = 0; i < 2; i++) {
        int vec = tid + i * 256;
        int r = vec >> 3, c = vec & 7;
        uint32_t d = buf + 2 * ABYTES + sw_off(r, c);
        size_t off = (size_t)r * ldb + k0 + c * 8;
        cpa16(d,         Bhi + off);
        cpa16(d + 8192,  Blo + off);
    }
}

template <int AROWS, int MT>
__device__ __forceinline__ void compute_chunk(uint32_t buf, int wm, int wn,
                                              int lane, float (*acc)[4])
{
    constexpr uint32_t ABYTES = AROWS * 128;
    const int lr = (lane & 7) + ((lane >> 3) & 1) * 8;
    const int lc = lane >> 4;
#pragma unroll
    for (int kk = 0; kk < 4; kk++) {
        const int c16 = kk * 2 + lc;
        uint32_t bh[4], bl[4];
        const int brow = wn * 16 + lr;
        ldsm4(bh, buf + 2 * ABYTES + sw_off(brow, c16));
        ldsm4(bl, buf + 2 * ABYTES + 8192 + sw_off(brow, c16));

        uint32_t ah[MT][4], al[MT][4];
#pragma unroll
        for (int mt = 0; mt < MT; mt++) {
            const int arow = wm * (MT * 16) + mt * 16 + lr;
            ldsm4(ah[mt], buf + sw_off(arow, c16));
            ldsm4(al[mt], buf + ABYTES + sw_off(arow, c16));
        }
#pragma unroll
        for (int mt = 0; mt < MT; mt++) {
            mma16816(acc[mt * 2 + 0], ah[mt], bh[0], bh[2]);
            mma16816(acc[mt * 2 + 1], ah[mt], bh[1], bh[3]);
        }
#pragma unroll
        for (int mt = 0; mt < MT; mt++) {
            mma16816(acc[mt * 2 + 0], ah[mt], bl[0], bl[2]);
            mma16816(acc[mt * 2 + 1], ah[mt], bl[1], bl[3]);
        }
#pragma unroll
        for (int mt = 0; mt < MT; mt++) {
            mma16816(acc[mt * 2 + 0], al[mt], bh[0], bh[2]);
            mma16816(acc[mt * 2 + 1], al[mt], bh[1], bh[3]);
        }
    }
}

// ---------------------------------------------------------------------------
// Init: zero h (fp32 + bf16 splits) and c
// ---------------------------------------------------------------------------
__global__ void zero_state_kernel() {
    int i = blockIdx.x * blockDim.x + threadIdx.x;
    if (i < B_ * H_) {
        g_h[i] = 0.0f;
        g_c[i] = 0.0f;
        g_hhi[i] = __float2bfloat16(0.0f);
        g_hlo[i] = __float2bfloat16(0.0f);
    }
}

// ---------------------------------------------------------------------------
// Prep: gate-permute + bf16-split Wh and Wx; permute bx; convert x to m-order.
// ---------------------------------------------------------------------------
__global__ void prep_kernel(const float* __restrict__ Wh,
                            const float* __restrict__ Wx,
                            const float* __restrict__ bx,
                            const float* __restrict__ x)
{
    int i = blockIdx.x * blockDim.x + threadIdx.x;
    if (i < G4 * H_) {
        int p = i >> 10;
        int k = i & (H_ - 1);
        int orig = ((p & 3) << 10) + (p >> 2);
        float w = Wh[(size_t)orig * H_ + k];
        __nv_bfloat16 hi = __float2bfloat16(w);
        g_Whp_hi[i] = hi;
        g_Whp_lo[i] = __float2bfloat16(w - __bfloat162float(hi));
    }
    if (i < T_ * B_ * D_) {
        int m = i >> 8;
        int k = i & (D_ - 1);
        int t = m >> 7;
        int b = m & 127;
        float v = x[((size_t)b * T_ + t) * D_ + k];
        __nv_bfloat16 hi = __float2bfloat16(v);
        g_xhi[i] = hi;
        g_xlo[i] = __float2bfloat16(v - __bfloat162float(hi));
    }
    if (i < G4 * D_) {
        int p = i >> 8;
        int k = i & (D_ - 1);
        int orig = ((p & 3) << 10) + (p >> 2);
        float w = Wx[(size_t)orig * D_ + k];
        __nv_bfloat16 hi = __float2bfloat16(w);
        g_Wxphi[i] = hi;
        g_Wxplo[i] = __float2bfloat16(w - __bfloat162float(hi));
    }
    if (i < G4) {
        int orig = ((i & 3) << 10) + (i >> 2);
        g_bxp[i] = bx[orig];
    }
}

// ---------------------------------------------------------------------------
// xg GEMM: g_xg[m][n] = xsplit[m] . Wxpsplit[n] + bxp[n]
// Grid: (64, 128), 256 thr. K = 256 = 4 chunks. AROWS=128, MT=4.
// ---------------------------------------------------------------------------
#define XG_BUF (2 * 128 * 128 + 2 * 8192)    // 49152
#define XG_SMEM (2 * XG_BUF)                 // 98304

__global__ void __launch_bounds__(256) xg_gemm_kernel()
{
    extern __shared__ char smem[];
    const uint32_t sb = smem_u32(smem);
    const int tid = threadIdx.x, lane = tid & 31, wid = tid >> 5;
    const int wm = wid & 1, wn = wid >> 1;
    const int n0 = blockIdx.x * 64;
    const int m0 = blockIdx.y * 128;

    const __nv_bfloat16* Ahi = g_xhi   + (size_t)m0 * D_;
    const __nv_bfloat16* Alo = g_xlo   + (size_t)m0 * D_;
    const __nv_bfloat16* Bhi = g_Wxphi + (size_t)n0 * D_;
    const __nv_bfloat16* Blo = g_Wxplo + (size_t)n0 * D_;

    float acc[8][4];
#pragma unroll
    for (int i = 0; i < 8; i++)
#pragma unroll
        for (int j = 0; j < 4; j++) acc[i][j] = 0.0f;

    load_chunk<128>(sb, Ahi, Alo, D_, Bhi, Blo, D_, 0, tid);
    CP_COMMIT();
#pragma unroll
    for (int c = 0; c < 4; c++) {
        if (c < 3) {
            load_chunk<128>(sb + ((c + 1) & 1) * XG_BUF, Ahi, Alo, D_,
                            Bhi, Blo, D_, (c + 1) * 64, tid);
            CP_COMMIT();
            CP_WAIT(1);
        } else {
            CP_WAIT(0);
        }
        __syncthreads();
        compute_chunk<128, 4>(sb + (c & 1) * XG_BUF, wm, wn, lane, acc);
        __syncthreads();
    }

#pragma unroll
    for (int mt = 0; mt < 4; mt++)
#pragma unroll
        for (int nt = 0; nt < 2; nt++) {
            int r   = m0 + wm * 64 + mt * 16 + (lane >> 2);
            int col = n0 + wn * 16 + nt * 8 + (lane & 3) * 2;
            float b0 = g_bxp[col], b1 = g_bxp[col + 1];
            const float* a = acc[mt * 2 + nt];
            *(float2*)(g_xg + (size_t)r * G4 + col) =
                make_float2(a[0] + b0, a[1] + b1);
            *(float2*)(g_xg + (size_t)(r + 8) * G4 + col) =
                make_float2(a[2] + b0, a[3] + b1);
        }
}

// ---------------------------------------------------------------------------
// Recurrent step: raw = h @ Whp^T (split-bf16 HMMA) + fused LSTM cell.
// Grid: (64, 2) = 128 CTAs x 512 threads (16 warps, 4x4 warp grid).
// CTA tile: M=64 x N=64, warp tile 16x16. K = 1024 = 16 chunks of 64.
// 3-stage cp.async pipeline, ONE __syncthreads per chunk.
// Buffer: Ahi[64][64] @0 | Alo @8192 | Bhi[64][64] @16384 | Blo @24576 = 32768 B
// ---------------------------------------------------------------------------
#define REC_BUF   32768
#define REC_SMEM  (3 * REC_BUF)   // 98304

__device__ __forceinline__ void rec_load(
    uint32_t buf,
    const __nv_bfloat16* __restrict__ Ahi, const __nv_bfloat16* __restrict__ Alo,
    const __nv_bfloat16* __restrict__ Bhi, const __nv_bfloat16* __restrict__ Blo,
    int k0, int tid)
{
    // 512 threads, 512 vec16 per array: exactly one vec per thread per array
    int r = tid >> 3, c = tid & 7;
    uint32_t d = buf + sw_off(r, c);
    size_t off = (size_t)r * H_ + k0 + c * 8;
    cpa16(d,          Ahi + off);
    cpa16(d + 8192,   Alo + off);
    cpa16(d + 16384,  Bhi + off);
    cpa16(d + 24576,  Blo + off);
}

__device__ __forceinline__ void rec_compute(uint32_t buf, int wm, int wn,
                                            int lane, float (*acc)[4])
{
    const int lr = (lane & 7) + ((lane >> 3) & 1) * 8;
    const int lc = lane >> 4;
#pragma unroll
    for (int kk = 0; kk < 4; kk++) {
        const int c16 = kk * 2 + lc;
        uint32_t ah[4], al[4], bh[4], bl[4];
        ldsm4(ah, buf +         sw_off(wm * 16 + lr, c16));
        ldsm4(al, buf +  8192 + sw_off(wm * 16 + lr, c16));
        ldsm4(bh, buf + 16384 + sw_off(wn * 16 + lr, c16));
        ldsm4(bl, buf + 24576 + sw_off(wn * 16 + lr, c16));
        // term-major; same-acc dependent MMAs separated by one independent MMA
        mma16816(acc[0], ah, bh[0], bh[2]);
        mma16816(acc[1], ah, bh[1], bh[3]);
        mma16816(acc[0], ah, bl[0], bl[2]);
        mma16816(acc[1], ah, bl[1], bl[3]);
        mma16816(acc[0], al, bh[0], bh[2]);
        mma16816(acc[1], al, bh[1], bh[3]);
    }
}

__global__ void __launch_bounds__(512) rec_step_kernel(const float* __restrict__ xg_t)
{
    extern __shared__ char smem[];
    const uint32_t sb = smem_u32(smem);
    const int tid = threadIdx.x, lane = tid & 31, wid = tid >> 5;
    const int wm = wid & 3, wn = wid >> 2;          // 4 x 4 warp grid
    const int n0 = blockIdx.x * 64;
    const int m0 = blockIdx.y * 64;

    const __nv_bfloat16* Ahi = g_hhi + (size_t)m0 * H_;
    const __nv_bfloat16* Alo = g_hlo + (size_t)m0 * H_;
    const __nv_bfloat16* Bhi = g_Whp_hi + (size_t)n0 * H_;
    const __nv_bfloat16* Blo = g_Whp_lo + (size_t)n0 * H_;

    float acc[2][4];
#pragma unroll
    for (int i = 0; i < 2; i++)
#pragma unroll
        for (int j = 0; j < 4; j++) acc[i][j] = 0.0f;

    // prologue: 2 chunks in flight
    rec_load(sb,           Ahi, Alo, Bhi, Blo, 0,  tid);
    CP_COMMIT();
    rec_load(sb + REC_BUF, Ahi, Alo, Bhi, Blo, 64, tid);
    CP_COMMIT();

#pragma unroll
    for (int c = 0; c < 16; c++) {
        if (c < 15) { CP_WAIT(1); } else { CP_WAIT(0); }
        __syncthreads();
        if (c + 2 < 16) {
            rec_load(sb + ((c + 2) % 3) * REC_BUF, Ahi, Alo, Bhi, Blo,
                     (c + 2) * 64, tid);
            CP_COMMIT();
        }
        rec_compute(sb + (c % 3) * REC_BUF, wm, wn, lane, acc);
    }
    __syncthreads();

    // Stage C in SMEM (stride 65 floats; reuses buffer region)
    float* Cs = (float*)smem;
#pragma unroll
    for (int nt = 0; nt < 2; nt++) {
        int r  = wm * 16 + (lane >> 2);
        int cc = wn * 16 + nt * 8 + (lane & 3) * 2;
        const float* a = acc[nt];
        Cs[r * 65 + cc]           = a[0];
        Cs[r * 65 + cc + 1]       = a[1];
        Cs[(r + 8) * 65 + cc]     = a[2];
        Cs[(r + 8) * 65 + cc + 1] = a[3];
    }
    __syncthreads();

    // Fused LSTM cell: 512 threads, 64 rows x 8 threads, 2 units each
    {
        const int br = tid >> 3;                 // 0..63 local batch row
        const int u0 = (tid & 7) * 2;            // unit group base
        const int b = m0 + br;
        const float4* xg4 = (const float4*)(xg_t + (size_t)b * G4 + n0);
        const int jbase = n0 >> 2;
#pragma unroll
        for (int uu = 0; uu < 2; uu++) {
            int u = u0 + uu;
            float4 xv = xg4[u];
            float gg = Cs[br * 65 + 4 * u + 0] + xv.x;
            float ii = Cs[br * 65 + 4 * u + 1] + xv.y;
            float ff = Cs[br * 65 + 4 * u + 2] + xv.z;
            float oo = Cs[br * 65 + 4 * u + 3] + xv.w;
            gg = tanhf(gg);
            ii = 1.0f / (1.0f + expf(-ii));
            ff = 1.0f / (1.0f + expf(-ff));
            oo = 1.0f / (1.0f + expf(-oo));
            int idx = b * H_ + jbase + u;
            float cn = fmaf(gg, ii, g_c[idx] * ff);
            g_c[idx] = cn;
            float hv = tanhf(cn) * oo;
            g_h[idx] = hv;
            __nv_bfloat16 hi = __float2bfloat16(hv);
            g_hhi[idx] = hi;
            g_hlo[idx] = __float2bfloat16(hv - __bfloat162float(hi));
        }
    }
}

// ---------------------------------------------------------------------------
// Final projection + softmax: one block per batch row
// ---------------------------------------------------------------------------
__global__ void __launch_bounds__(256) proj_softmax_kernel(
    const float* __restrict__ h, const float* __restrict__ Wp,
    const float* __restrict__ bp, float* __restrict__ out)
{
    __shared__ float hs[H_];
    __shared__ float logits[O_];
    __shared__ float red[8];

    const int b = blockIdx.x;
    const int tid = threadIdx.x;
    const int lane = tid & 31;
    const int warp = tid >> 5;

    for (int k = tid; k < H_; k += 256) hs[k] = h[b * H_ + k];
    __syncthreads();

    for (int o = warp; o < O_; o += 8) {
        const float4* w = (const float4*)(Wp + (size_t)o * H_);
        const float4* hv4 = (const float4*)hs;
        float s = 0.0f;
        for (int k4 = lane; k4 < H_ / 4; k4 += 32) {
            float4 wv = w[k4];
            float4 hv = hv4[k4];
            s = fmaf(wv.x, hv.x, s);
            s = fmaf(wv.y, hv.y, s);
            s = fmaf(wv.z, hv.z, s);
            s = fmaf(wv.w, hv.w, s);
        }
#pragma unroll
        for (int d = 16; d; d >>= 1) s += __shfl_xor_sync(0xFFFFFFFFu, s, d);
        if (lane == 0) logits[o] = s + bp[o];
    }
    __syncthreads();

    float mx = -INFINITY;
    for (int o = tid; o < O_; o += 256) mx = fmaxf(mx, logits[o]);
#pragma unroll
    for (int d = 16; d; d >>= 1) mx = fmaxf(mx, __shfl_xor_sync(0xFFFFFFFFu, mx, d));
    if (lane == 0) red[warp] = mx;
    __syncthreads();
    if (warp == 0) {
        float v = (lane < 8) ? red[lane] : -INFINITY;
#pragma unroll
        for (int d = 4; d; d >>= 1) v = fmaxf(v, __shfl_xor_sync(0xFFFFFFFFu, v, d));
        if (lane == 0) red[0] = v;
    }
    __syncthreads();
    mx = red[0];
    __syncthreads();

    float sm = 0.0f;
    for (int o = tid; o < O_; o += 256) {
        float e = expf(logits[o] - mx);
        logits[o] = e;
        sm += e;
    }
#pragma unroll
    for (int d = 16; d; d >>= 1) sm += __shfl_xor_sync(0xFFFFFFFFu, sm, d);
    if (lane == 0) red[warp] = sm;
    __syncthreads();
    if (warp == 0) {
        float v = (lane < 8) ? red[lane] : 0.0f;
#pragma unroll
        for (int d = 4; d; d >>= 1) v += __shfl_xor_sync(0xFFFFFFFFu, v, d);
        if (lane == 0) red[0] = v;
    }
    __syncthreads();
    float inv = 1.0f / red[0];

    for (int o = tid; o < O_; o += 256)
        out[(size_t)b * O_ + o] = logits[o] * inv;
}

// ---------------------------------------------------------------------------
// kernel_launch
// Inputs: x[B,T,D], Wx[4H,D], bx[4H], Wh[4H,H], Wp[O,H], bp[O]
// ---------------------------------------------------------------------------
extern "C" void kernel_launch(void* const* d_in, const int* in_sizes, int n_in,
                              void* d_out, int out_size)
{
    (void)in_sizes; (void)n_in; (void)out_size;
    const float* x  = (const float*)d_in[0];
    const float* Wx = (const float*)d_in[1];
    const float* bx = (const float*)d_in[2];
    const float* Wh = (const float*)d_in[3];
    const float* Wp = (const float*)d_in[4];
    const float* bp = (const float*)d_in[5];
    float* out = (float*)d_out;

    cudaFuncSetAttribute(rec_step_kernel,
                         cudaFuncAttributeMaxDynamicSharedMemorySize, REC_SMEM);
    cudaFuncSetAttribute(xg_gemm_kernel,
                         cudaFuncAttributeMaxDynamicSharedMemorySize, XG_SMEM);

    float *xg, *h;
    cudaGetSymbolAddress((void**)&xg, g_xg);
    cudaGetSymbolAddress((void**)&h,  g_h);

    // 1. zero state
    zero_state_kernel<<<(B_ * H_ + 255) / 256, 256>>>();

    // 2. weight/x prep (gate permutation + bf16 split)
    prep_kernel<<<(G4 * H_ + 255) / 256, 256>>>(Wh, Wx, bx, x);

    // 3. xg = xsplit @ Wxpsplit^T + bxp  (HMMA, permuted gate columns)
    {
        dim3 grid(G4 / 64, (T_ * B_) / 128);
        xg_gemm_kernel<<<grid, 256, XG_SMEM>>>();
    }

    // 4. recurrence: HMMA GEMM + fused cell, 128 CTAs x 512 threads per step
    {
        dim3 grid(G4 / 64, B_ / 64);
        for (int t = 0; t < T_; t++) {
            rec_step_kernel<<<grid, 512, REC_SMEM>>>(xg + (size_t)t * B_ * G4);
        }
    }

    // 5. projection + softmax
    proj_softmax_kernel<<<B_, 256>>>(h, Wp, bp, out);
}